// round 7
// baseline (speedup 1.0000x reference)
#include <cuda_runtime.h>
#include <cuda_bf16.h>

// CompositeValueNoise, spatially-binned v5.
// vs R6: hist pass keeps the atomicAdd return value as the point's in-bucket
// RANK (coalesced 4B store). scan1 turns counts into absolute exclusive bases
// in place. Scatter then has NO atomics: pos = base[key] (4B gather) + rank.
// This removes 2M L2 atomic RMWs (~128 MB of L2 traffic) from scatter, which
// R6 showed to be L2-traffic bound (50.6% L2, 4% issue).

#define N_FIELDS 4
#define MAXN 2000000
#define BBITS 7
#define BDIM (1 << BBITS)            // 128
#define NBUCK (BDIM * BDIM * BDIM)   // 2097152
#define SCAN_BLKS (NBUCK / 1024)     // 2048

__device__ int    g_hist[NBUCK];
__device__ int    g_counter;
__device__ int    g_rank[MAXN];
__device__ float4 g_sorted[MAXN];

__device__ __forceinline__ int cell_key(float px, float py, float pz) {
    int ci = min(max((int)(px * (float)BDIM), 0), BDIM - 1);
    int cj = min(max((int)(py * (float)BDIM), 0), BDIM - 1);
    int ck = min(max((int)(pz * (float)BDIM), 0), BDIM - 1);
    return (ci << (2 * BBITS)) | (cj << BBITS) | ck;   // k innermost
}

__global__ void zero_hist_kernel() {
    int i = blockIdx.x * blockDim.x + threadIdx.x;
    if (i < NBUCK / 4)
        reinterpret_cast<int4*>(g_hist)[i] = make_int4(0, 0, 0, 0);
    if (i == 0) g_counter = 0;
}

// Histogram; atomicAdd return value = this point's rank within its bucket.
__global__ void hist_kernel(const float* __restrict__ x, int n) {
    int t = blockIdx.x * blockDim.x + threadIdx.x;
    int p0 = t * 4;
    if (p0 >= n) return;
    if (p0 + 4 <= n) {
        const float4* xv = reinterpret_cast<const float4*>(x) + 3 * (size_t)t;
        float4 a = __ldg(xv + 0), b = __ldg(xv + 1), c = __ldg(xv + 2);
        int4 r;
        r.x = atomicAdd(&g_hist[cell_key(a.x, a.y, a.z)], 1);
        r.y = atomicAdd(&g_hist[cell_key(a.w, b.x, b.y)], 1);
        r.z = atomicAdd(&g_hist[cell_key(b.z, b.w, c.x)], 1);
        r.w = atomicAdd(&g_hist[cell_key(c.y, c.z, c.w)], 1);
        *reinterpret_cast<int4*>(&g_rank[p0]) = r;   // coalesced
    } else {
        for (int p = p0; p < n; ++p)
            g_rank[p] = atomicAdd(&g_hist[cell_key(x[3*p], x[3*p+1], x[3*p+2])], 1);
    }
}

// Coalesced block scan of 1024 ints; block grabs its global segment base via
// one early atomicAdd on g_counter and folds it in, so g_hist ends holding
// ABSOLUTE exclusive bucket bases. Segment order is run-arbitrary; each
// point's final slot and value are unchanged -> deterministic output.
__global__ void scan1_kernel() {
    __shared__ int warp_sums[8];
    __shared__ int s_base;
    int b = blockIdx.x, t = threadIdx.x;
    int lane = t & 31, wid = t >> 5;
    int base = b * 1024 + t * 4;

    int4 v = *reinterpret_cast<int4*>(&g_hist[base]);
    int tot = v.x + v.y + v.z + v.w;

    int inc = tot;
    #pragma unroll
    for (int o = 1; o < 32; o <<= 1) {
        int u = __shfl_up_sync(0xffffffffu, inc, o);
        if (lane >= o) inc += u;
    }
    if (lane == 31) warp_sums[wid] = inc;
    __syncthreads();
    if (wid == 0 && lane < 8) {
        int w = warp_sums[lane];
        #pragma unroll
        for (int o = 1; o < 8; o <<= 1) {
            int u = __shfl_up_sync(0xffu, w, o);
            if (lane >= o) w += u;
        }
        warp_sums[lane] = w;
        if (lane == 7) s_base = atomicAdd(&g_counter, w);  // w == block total
    }
    __syncthreads();
    int excl = s_base + (wid ? warp_sums[wid - 1] : 0) + inc - tot;

    int4 r;
    r.x = excl;
    r.y = excl + v.x;
    r.z = excl + v.x + v.y;
    r.w = excl + v.x + v.y + v.z;
    *reinterpret_cast<int4*>(&g_hist[base]) = r;
}

// No atomics: pos = base[key] (plain gather) + precomputed rank.
__device__ __forceinline__ void scatter_one(float px, float py, float pz,
                                            int rank, int i) {
    int pos = __ldg(&g_hist[cell_key(px, py, pz)]) + rank;
    g_sorted[pos] = make_float4(px, py, pz, __int_as_float(i));
}

__global__ void scatter_kernel(const float* __restrict__ x, int n) {
    int t = blockIdx.x * blockDim.x + threadIdx.x;
    int p0 = t * 4;
    if (p0 >= n) return;
    if (p0 + 4 <= n) {
        const float4* xv = reinterpret_cast<const float4*>(x) + 3 * (size_t)t;
        float4 a = __ldg(xv + 0), b = __ldg(xv + 1), c = __ldg(xv + 2);
        int4 rk = *reinterpret_cast<const int4*>(&g_rank[p0]);
        scatter_one(a.x, a.y, a.z, rk.x, p0 + 0);
        scatter_one(a.w, b.x, b.y, rk.y, p0 + 1);
        scatter_one(b.z, b.w, c.x, rk.z, p0 + 2);
        scatter_one(c.y, c.z, c.w, rk.w, p0 + 3);
    } else {
        for (int p = p0; p < n; ++p)
            scatter_one(x[3*p], x[3*p+1], x[3*p+2], g_rank[p], p);
    }
}

__device__ __forceinline__ float4 ld4(const float* __restrict__ p) {
    return __ldg(reinterpret_cast<const float4*>(p));
}

__device__ __forceinline__ float4 lerp4(float4 a, float4 b, float w) {
    float4 r;
    r.x = fmaf(w, b.x - a.x, a.x);
    r.y = fmaf(w, b.y - a.y, a.y);
    r.z = fmaf(w, b.z - a.z, a.z);
    r.w = fmaf(w, b.w - a.w, a.w);
    return r;
}

struct Lv {
    const float* base;
    int s0, s1;
    float wx, wy, wz;
};

__device__ __forceinline__ Lv prep(const float* __restrict__ V, int res,
                                   float px, float py, float pz, int kk) {
    const float resf = (float)res;
    float xs = px * resf, ys = py * resf, zs = pz * resf;
    float fx = floorf(xs), fy = floorf(ys), fz = floorf(zs);
    float tx = xs - fx,    ty = ys - fy,    tz = zs - fz;
    int i0 = (int)fx, j0 = (int)fy, k0 = (int)fz;
    Lv L;
    L.wx = (3.0f - 2.0f * tx) * tx * tx;
    L.wy = (3.0f - 2.0f * ty) * ty * ty;
    L.wz = (3.0f - 2.0f * tz) * tz * tz;
    const int r1 = res + 1;
    L.s1 = r1 * N_FIELDS;
    L.s0 = r1 * L.s1;
    L.base = V + (size_t)i0 * L.s0 + (size_t)j0 * L.s1
               + (size_t)(k0 + kk) * N_FIELDS;
    return L;
}

__device__ __forceinline__ void do_loads(const Lv& L, float4 v[4]) {
    v[0] = ld4(L.base);
    v[1] = ld4(L.base + L.s1);
    v[2] = ld4(L.base + L.s0);
    v[3] = ld4(L.base + L.s0 + L.s1);
}

__device__ __forceinline__ float4 interp(const Lv& L, const float4 v[4], int kk) {
    float4 a0 = lerp4(v[0], v[2], L.wx);
    float4 a1 = lerp4(v[1], v[3], L.wx);
    float4 b  = lerp4(a0, a1, L.wy);
    float4 o;
    o.x = __shfl_xor_sync(0xffffffffu, b.x, 1);
    o.y = __shfl_xor_sync(0xffffffffu, b.y, 1);
    o.z = __shfl_xor_sync(0xffffffffu, b.z, 1);
    o.w = __shfl_xor_sync(0xffffffffu, b.w, 1);
    float4 lo = kk ? o : b;
    float4 hi = kk ? b : o;
    return lerp4(lo, hi, L.wz);
}

__global__ void __launch_bounds__(256) composite_value_noise_kernel(
    const float* __restrict__ V16,
    const float* __restrict__ V32,
    const float* __restrict__ V64,
    const float* __restrict__ V128,
    float* __restrict__ out,
    int n)
{
    int gtid = blockIdx.x * blockDim.x + threadIdx.x;
    int p  = gtid >> 1;
    int kk = gtid & 1;
    if (p >= n) return;

    float4 pt = g_sorted[p];
    const float px = pt.x, py = pt.y, pz = pt.z;
    const int   idx = __float_as_int(pt.w);

    Lv l0 = prep(V16, 16, px, py, pz, kk);
    Lv l1 = prep(V32, 32, px, py, pz, kk);
    float4 va[4], vb[4];
    do_loads(l0, va);
    do_loads(l1, vb);
    float4 n0 = interp(l0, va, kk);
    float4 n1 = interp(l1, vb, kk);

    Lv l2 = prep(V64, 64, px, py, pz, kk);
    Lv l3 = prep(V128, 128, px, py, pz, kk);
    do_loads(l2, va);
    do_loads(l3, vb);
    float4 n2 = interp(l2, va, kk);
    float4 n3 = interp(l3, vb, kk);

    float4 acc;
    acc.x = fmaf(0.125f, n3.x, fmaf(0.25f, n2.x, fmaf(0.5f, n1.x, n0.x)));
    acc.y = fmaf(0.125f, n3.y, fmaf(0.25f, n2.y, fmaf(0.5f, n1.y, n0.y)));
    acc.z = fmaf(0.125f, n3.z, fmaf(0.25f, n2.z, fmaf(0.5f, n1.z, n0.z)));
    acc.w = fmaf(0.125f, n3.w, fmaf(0.25f, n2.w, fmaf(0.5f, n1.w, n0.w)));

    float2 half_val = kk ? make_float2(acc.z, acc.w) : make_float2(acc.x, acc.y);
    reinterpret_cast<float2*>(out)[2 * (size_t)idx + kk] = half_val;
}

extern "C" void kernel_launch(void* const* d_in, const int* in_sizes, int n_in,
                              void* d_out, int out_size) {
    const float* x    = (const float*)d_in[0];
    const float* V16  = (const float*)d_in[1];
    const float* V32  = (const float*)d_in[2];
    const float* V64  = (const float*)d_in[3];
    const float* V128 = (const float*)d_in[4];
    float* out = (float*)d_out;

    int n = in_sizes[0] / 3;
    const int T = 256;
    int nquads = (n + 3) / 4;

    zero_hist_kernel<<<(NBUCK / 4 + T - 1) / T, T>>>();
    hist_kernel<<<(nquads + T - 1) / T, T>>>(x, n);
    scan1_kernel<<<SCAN_BLKS, 256>>>();
    scatter_kernel<<<(nquads + T - 1) / T, T>>>(x, n);

    long long total = 2LL * n;
    int blocks = (int)((total + T - 1) / T);
    composite_value_noise_kernel<<<blocks, T>>>(V16, V32, V64, V128, out, n);
}

// round 8
// speedup vs baseline: 1.0769x; 1.0769x over previous
#include <cuda_runtime.h>
#include <cuda_bf16.h>

// CompositeValueNoise, spatially-binned v6.
// vs R6/R7: revert the rank split (R7 regressed), shrink bins to BBITS=6 so
// the hist table is 1 MB (L2-hot): zero and scan become ~free, hist/scatter
// atomics stop missing. Main kernel keeps 2-lanes-per-point + sorted input.

#define N_FIELDS 4
#define MAXN 2000000
#define BBITS 6
#define BDIM (1 << BBITS)            // 64
#define NBUCK (BDIM * BDIM * BDIM)   // 262144
#define SCAN_BLKS (NBUCK / 1024)     // 256

__device__ int    g_hist[NBUCK];
__device__ int    g_counter;
__device__ float4 g_sorted[MAXN];

__device__ __forceinline__ int cell_key(float px, float py, float pz) {
    int ci = min(max((int)(px * (float)BDIM), 0), BDIM - 1);
    int cj = min(max((int)(py * (float)BDIM), 0), BDIM - 1);
    int ck = min(max((int)(pz * (float)BDIM), 0), BDIM - 1);
    return (ci << (2 * BBITS)) | (cj << BBITS) | ck;   // k innermost
}

__global__ void zero_hist_kernel() {
    int i = blockIdx.x * blockDim.x + threadIdx.x;
    if (i < NBUCK / 4)
        reinterpret_cast<int4*>(g_hist)[i] = make_int4(0, 0, 0, 0);
    if (i == 0) g_counter = 0;
}

__global__ void hist_kernel(const float* __restrict__ x, int n) {
    int t = blockIdx.x * blockDim.x + threadIdx.x;
    int p0 = t * 4;
    if (p0 >= n) return;
    if (p0 + 4 <= n) {
        const float4* xv = reinterpret_cast<const float4*>(x) + 3 * (size_t)t;
        float4 a = __ldg(xv + 0), b = __ldg(xv + 1), c = __ldg(xv + 2);
        atomicAdd(&g_hist[cell_key(a.x, a.y, a.z)], 1);
        atomicAdd(&g_hist[cell_key(a.w, b.x, b.y)], 1);
        atomicAdd(&g_hist[cell_key(b.z, b.w, c.x)], 1);
        atomicAdd(&g_hist[cell_key(c.y, c.z, c.w)], 1);
    } else {
        for (int p = p0; p < n; ++p)
            atomicAdd(&g_hist[cell_key(x[3*p], x[3*p+1], x[3*p+2])], 1);
    }
}

// Coalesced block scan of 1024 ints; each block takes its global segment base
// via one early atomicAdd on g_counter, folding it into the stored prefixes.
// g_hist ends holding ABSOLUTE exclusive bucket bases. Segment order is
// run-arbitrary; each point's slot and value are unchanged -> deterministic.
__global__ void scan1_kernel() {
    __shared__ int warp_sums[8];
    __shared__ int s_base;
    int b = blockIdx.x, t = threadIdx.x;
    int lane = t & 31, wid = t >> 5;
    int base = b * 1024 + t * 4;

    int4 v = *reinterpret_cast<int4*>(&g_hist[base]);
    int tot = v.x + v.y + v.z + v.w;

    int inc = tot;
    #pragma unroll
    for (int o = 1; o < 32; o <<= 1) {
        int u = __shfl_up_sync(0xffffffffu, inc, o);
        if (lane >= o) inc += u;
    }
    if (lane == 31) warp_sums[wid] = inc;
    __syncthreads();
    if (wid == 0 && lane < 8) {
        int w = warp_sums[lane];
        #pragma unroll
        for (int o = 1; o < 8; o <<= 1) {
            int u = __shfl_up_sync(0xffu, w, o);
            if (lane >= o) w += u;
        }
        warp_sums[lane] = w;
        if (lane == 7) s_base = atomicAdd(&g_counter, w);  // w == block total
    }
    __syncthreads();
    int excl = s_base + (wid ? warp_sums[wid - 1] : 0) + inc - tot;

    int4 r;
    r.x = excl;
    r.y = excl + v.x;
    r.z = excl + v.x + v.y;
    r.w = excl + v.x + v.y + v.z;
    *reinterpret_cast<int4*>(&g_hist[base]) = r;
}

__device__ __forceinline__ void scatter_one(float px, float py, float pz, int i) {
    int pos = atomicAdd(&g_hist[cell_key(px, py, pz)], 1);
    g_sorted[pos] = make_float4(px, py, pz, __int_as_float(i));
}

__global__ void scatter_kernel(const float* __restrict__ x, int n) {
    int t = blockIdx.x * blockDim.x + threadIdx.x;
    int p0 = t * 4;
    if (p0 >= n) return;
    if (p0 + 4 <= n) {
        const float4* xv = reinterpret_cast<const float4*>(x) + 3 * (size_t)t;
        float4 a = __ldg(xv + 0), b = __ldg(xv + 1), c = __ldg(xv + 2);
        scatter_one(a.x, a.y, a.z, p0 + 0);
        scatter_one(a.w, b.x, b.y, p0 + 1);
        scatter_one(b.z, b.w, c.x, p0 + 2);
        scatter_one(c.y, c.z, c.w, p0 + 3);
    } else {
        for (int p = p0; p < n; ++p)
            scatter_one(x[3*p], x[3*p+1], x[3*p+2], p);
    }
}

__device__ __forceinline__ float4 ld4(const float* __restrict__ p) {
    return __ldg(reinterpret_cast<const float4*>(p));
}

__device__ __forceinline__ float4 lerp4(float4 a, float4 b, float w) {
    float4 r;
    r.x = fmaf(w, b.x - a.x, a.x);
    r.y = fmaf(w, b.y - a.y, a.y);
    r.z = fmaf(w, b.z - a.z, a.z);
    r.w = fmaf(w, b.w - a.w, a.w);
    return r;
}

struct Lv {
    const float* base;
    int s0, s1;
    float wx, wy, wz;
};

__device__ __forceinline__ Lv prep(const float* __restrict__ V, int res,
                                   float px, float py, float pz, int kk) {
    const float resf = (float)res;
    float xs = px * resf, ys = py * resf, zs = pz * resf;
    float fx = floorf(xs), fy = floorf(ys), fz = floorf(zs);
    float tx = xs - fx,    ty = ys - fy,    tz = zs - fz;
    int i0 = (int)fx, j0 = (int)fy, k0 = (int)fz;
    Lv L;
    L.wx = (3.0f - 2.0f * tx) * tx * tx;
    L.wy = (3.0f - 2.0f * ty) * ty * ty;
    L.wz = (3.0f - 2.0f * tz) * tz * tz;
    const int r1 = res + 1;
    L.s1 = r1 * N_FIELDS;
    L.s0 = r1 * L.s1;
    L.base = V + (size_t)i0 * L.s0 + (size_t)j0 * L.s1
               + (size_t)(k0 + kk) * N_FIELDS;
    return L;
}

__device__ __forceinline__ void do_loads(const Lv& L, float4 v[4]) {
    v[0] = ld4(L.base);
    v[1] = ld4(L.base + L.s1);
    v[2] = ld4(L.base + L.s0);
    v[3] = ld4(L.base + L.s0 + L.s1);
}

__device__ __forceinline__ float4 interp(const Lv& L, const float4 v[4], int kk) {
    float4 a0 = lerp4(v[0], v[2], L.wx);
    float4 a1 = lerp4(v[1], v[3], L.wx);
    float4 b  = lerp4(a0, a1, L.wy);
    float4 o;
    o.x = __shfl_xor_sync(0xffffffffu, b.x, 1);
    o.y = __shfl_xor_sync(0xffffffffu, b.y, 1);
    o.z = __shfl_xor_sync(0xffffffffu, b.z, 1);
    o.w = __shfl_xor_sync(0xffffffffu, b.w, 1);
    float4 lo = kk ? o : b;
    float4 hi = kk ? b : o;
    return lerp4(lo, hi, L.wz);
}

__global__ void __launch_bounds__(256) composite_value_noise_kernel(
    const float* __restrict__ V16,
    const float* __restrict__ V32,
    const float* __restrict__ V64,
    const float* __restrict__ V128,
    float* __restrict__ out,
    int n)
{
    int gtid = blockIdx.x * blockDim.x + threadIdx.x;
    int p  = gtid >> 1;
    int kk = gtid & 1;
    if (p >= n) return;

    float4 pt = g_sorted[p];
    const float px = pt.x, py = pt.y, pz = pt.z;
    const int   idx = __float_as_int(pt.w);

    Lv l0 = prep(V16, 16, px, py, pz, kk);
    Lv l1 = prep(V32, 32, px, py, pz, kk);
    float4 va[4], vb[4];
    do_loads(l0, va);
    do_loads(l1, vb);
    float4 n0 = interp(l0, va, kk);
    float4 n1 = interp(l1, vb, kk);

    Lv l2 = prep(V64, 64, px, py, pz, kk);
    Lv l3 = prep(V128, 128, px, py, pz, kk);
    do_loads(l2, va);
    do_loads(l3, vb);
    float4 n2 = interp(l2, va, kk);
    float4 n3 = interp(l3, vb, kk);

    float4 acc;
    acc.x = fmaf(0.125f, n3.x, fmaf(0.25f, n2.x, fmaf(0.5f, n1.x, n0.x)));
    acc.y = fmaf(0.125f, n3.y, fmaf(0.25f, n2.y, fmaf(0.5f, n1.y, n0.y)));
    acc.z = fmaf(0.125f, n3.z, fmaf(0.25f, n2.z, fmaf(0.5f, n1.z, n0.z)));
    acc.w = fmaf(0.125f, n3.w, fmaf(0.25f, n2.w, fmaf(0.5f, n1.w, n0.w)));

    float2 half_val = kk ? make_float2(acc.z, acc.w) : make_float2(acc.x, acc.y);
    reinterpret_cast<float2*>(out)[2 * (size_t)idx + kk] = half_val;
}

extern "C" void kernel_launch(void* const* d_in, const int* in_sizes, int n_in,
                              void* d_out, int out_size) {
    const float* x    = (const float*)d_in[0];
    const float* V16  = (const float*)d_in[1];
    const float* V32  = (const float*)d_in[2];
    const float* V64  = (const float*)d_in[3];
    const float* V128 = (const float*)d_in[4];
    float* out = (float*)d_out;

    int n = in_sizes[0] / 3;
    const int T = 256;
    int nquads = (n + 3) / 4;

    zero_hist_kernel<<<(NBUCK / 4 + T - 1) / T, T>>>();
    hist_kernel<<<(nquads + T - 1) / T, T>>>(x, n);
    scan1_kernel<<<SCAN_BLKS, 256>>>();
    scatter_kernel<<<(nquads + T - 1) / T, T>>>(x, n);

    long long total = 2LL * n;
    int blocks = (int)((total + T - 1) / T);
    composite_value_noise_kernel<<<blocks, T>>>(V16, V32, V64, V128, out, n);
}

// round 9
// speedup vs baseline: 1.1627x; 1.0797x over previous
#include <cuda_runtime.h>
#include <cuda_bf16.h>

// CompositeValueNoise, spatially-binned v7.
// vs R8: main kernel back to 1 THREAD PER POINT. On sorted input the
// lane-pair k-split is redundant (warp neighbors already share the same
// cells/lines), so dropping it removes 16 shuffles + half the per-point
// instruction overhead at equal wavefront cost. Sort pipeline unchanged
// (BBITS=6, atomic scatter, absolute bases via early-atomic scan).

#define N_FIELDS 4
#define MAXN 2000000
#define BBITS 6
#define BDIM (1 << BBITS)            // 64
#define NBUCK (BDIM * BDIM * BDIM)   // 262144
#define SCAN_BLKS (NBUCK / 1024)     // 256

__device__ int    g_hist[NBUCK];
__device__ int    g_counter;
__device__ float4 g_sorted[MAXN];

__device__ __forceinline__ int cell_key(float px, float py, float pz) {
    int ci = min(max((int)(px * (float)BDIM), 0), BDIM - 1);
    int cj = min(max((int)(py * (float)BDIM), 0), BDIM - 1);
    int ck = min(max((int)(pz * (float)BDIM), 0), BDIM - 1);
    return (ci << (2 * BBITS)) | (cj << BBITS) | ck;   // k innermost
}

__global__ void zero_hist_kernel() {
    int i = blockIdx.x * blockDim.x + threadIdx.x;
    if (i < NBUCK / 4)
        reinterpret_cast<int4*>(g_hist)[i] = make_int4(0, 0, 0, 0);
    if (i == 0) g_counter = 0;
}

__global__ void hist_kernel(const float* __restrict__ x, int n) {
    int t = blockIdx.x * blockDim.x + threadIdx.x;
    int p0 = t * 4;
    if (p0 >= n) return;
    if (p0 + 4 <= n) {
        const float4* xv = reinterpret_cast<const float4*>(x) + 3 * (size_t)t;
        float4 a = __ldg(xv + 0), b = __ldg(xv + 1), c = __ldg(xv + 2);
        atomicAdd(&g_hist[cell_key(a.x, a.y, a.z)], 1);
        atomicAdd(&g_hist[cell_key(a.w, b.x, b.y)], 1);
        atomicAdd(&g_hist[cell_key(b.z, b.w, c.x)], 1);
        atomicAdd(&g_hist[cell_key(c.y, c.z, c.w)], 1);
    } else {
        for (int p = p0; p < n; ++p)
            atomicAdd(&g_hist[cell_key(x[3*p], x[3*p+1], x[3*p+2])], 1);
    }
}

// Coalesced block scan of 1024 ints; block takes its global segment base via
// one early atomicAdd on g_counter, folded into the stored prefixes, so
// g_hist ends holding ABSOLUTE exclusive bucket bases. Segment order is
// run-arbitrary; each point's slot and value are unchanged -> deterministic.
__global__ void scan1_kernel() {
    __shared__ int warp_sums[8];
    __shared__ int s_base;
    int b = blockIdx.x, t = threadIdx.x;
    int lane = t & 31, wid = t >> 5;
    int base = b * 1024 + t * 4;

    int4 v = *reinterpret_cast<int4*>(&g_hist[base]);
    int tot = v.x + v.y + v.z + v.w;

    int inc = tot;
    #pragma unroll
    for (int o = 1; o < 32; o <<= 1) {
        int u = __shfl_up_sync(0xffffffffu, inc, o);
        if (lane >= o) inc += u;
    }
    if (lane == 31) warp_sums[wid] = inc;
    __syncthreads();
    if (wid == 0 && lane < 8) {
        int w = warp_sums[lane];
        #pragma unroll
        for (int o = 1; o < 8; o <<= 1) {
            int u = __shfl_up_sync(0xffu, w, o);
            if (lane >= o) w += u;
        }
        warp_sums[lane] = w;
        if (lane == 7) s_base = atomicAdd(&g_counter, w);  // w == block total
    }
    __syncthreads();
    int excl = s_base + (wid ? warp_sums[wid - 1] : 0) + inc - tot;

    int4 r;
    r.x = excl;
    r.y = excl + v.x;
    r.z = excl + v.x + v.y;
    r.w = excl + v.x + v.y + v.z;
    *reinterpret_cast<int4*>(&g_hist[base]) = r;
}

__device__ __forceinline__ void scatter_one(float px, float py, float pz, int i) {
    int pos = atomicAdd(&g_hist[cell_key(px, py, pz)], 1);
    g_sorted[pos] = make_float4(px, py, pz, __int_as_float(i));
}

__global__ void scatter_kernel(const float* __restrict__ x, int n) {
    int t = blockIdx.x * blockDim.x + threadIdx.x;
    int p0 = t * 4;
    if (p0 >= n) return;
    if (p0 + 4 <= n) {
        const float4* xv = reinterpret_cast<const float4*>(x) + 3 * (size_t)t;
        float4 a = __ldg(xv + 0), b = __ldg(xv + 1), c = __ldg(xv + 2);
        scatter_one(a.x, a.y, a.z, p0 + 0);
        scatter_one(a.w, b.x, b.y, p0 + 1);
        scatter_one(b.z, b.w, c.x, p0 + 2);
        scatter_one(c.y, c.z, c.w, p0 + 3);
    } else {
        for (int p = p0; p < n; ++p)
            scatter_one(x[3*p], x[3*p+1], x[3*p+2], p);
    }
}

__device__ __forceinline__ float4 ld4(const float* __restrict__ p) {
    return __ldg(reinterpret_cast<const float4*>(p));
}

__device__ __forceinline__ float4 lerp4(float4 a, float4 b, float w) {
    float4 r;
    r.x = fmaf(w, b.x - a.x, a.x);
    r.y = fmaf(w, b.y - a.y, a.y);
    r.z = fmaf(w, b.z - a.z, a.z);
    r.w = fmaf(w, b.w - a.w, a.w);
    return r;
}

struct Lv {
    const float* base;
    int s0, s1;
    float wx, wy, wz;
};

__device__ __forceinline__ Lv prep(const float* __restrict__ V, int res,
                                   float px, float py, float pz) {
    const float resf = (float)res;
    float xs = px * resf, ys = py * resf, zs = pz * resf;
    float fx = floorf(xs), fy = floorf(ys), fz = floorf(zs);
    float tx = xs - fx,    ty = ys - fy,    tz = zs - fz;
    int i0 = (int)fx, j0 = (int)fy, k0 = (int)fz;
    Lv L;
    L.wx = (3.0f - 2.0f * tx) * tx * tx;
    L.wy = (3.0f - 2.0f * ty) * ty * ty;
    L.wz = (3.0f - 2.0f * tz) * tz * tz;
    const int r1 = res + 1;
    L.s1 = r1 * N_FIELDS;
    L.s0 = r1 * L.s1;
    L.base = V + (size_t)i0 * L.s0 + (size_t)j0 * L.s1 + (size_t)k0 * N_FIELDS;
    return L;
}

// 8 corner loads for one level, batched.
__device__ __forceinline__ void do_loads8(const Lv& L, float4 v[8]) {
    v[0] = ld4(L.base);
    v[1] = ld4(L.base + N_FIELDS);
    v[2] = ld4(L.base + L.s1);
    v[3] = ld4(L.base + L.s1 + N_FIELDS);
    v[4] = ld4(L.base + L.s0);
    v[5] = ld4(L.base + L.s0 + N_FIELDS);
    v[6] = ld4(L.base + L.s0 + L.s1);
    v[7] = ld4(L.base + L.s0 + L.s1 + N_FIELDS);
}

__device__ __forceinline__ float4 interp8(const Lv& L, const float4 v[8]) {
    // reference order: dim0 (wx), dim1 (wy), dim2 (wz)
    float4 a00 = lerp4(v[0], v[4], L.wx);
    float4 a01 = lerp4(v[1], v[5], L.wx);
    float4 a10 = lerp4(v[2], v[6], L.wx);
    float4 a11 = lerp4(v[3], v[7], L.wx);
    float4 b0 = lerp4(a00, a10, L.wy);
    float4 b1 = lerp4(a01, a11, L.wy);
    return lerp4(b0, b1, L.wz);
}

__global__ void __launch_bounds__(256) composite_value_noise_kernel(
    const float* __restrict__ V16,
    const float* __restrict__ V32,
    const float* __restrict__ V64,
    const float* __restrict__ V128,
    float* __restrict__ out,
    int n)
{
    int p = blockIdx.x * blockDim.x + threadIdx.x;
    if (p >= n) return;

    float4 pt = g_sorted[p];
    const float px = pt.x, py = pt.y, pz = pt.z;
    const int   idx = __float_as_int(pt.w);

    // Pair 1: V16 + V32 — 16 loads issued before interpolation math.
    Lv l0 = prep(V16, 16, px, py, pz);
    Lv l1 = prep(V32, 32, px, py, pz);
    float4 va[8], vb[8];
    do_loads8(l0, va);
    do_loads8(l1, vb);
    float4 n0 = interp8(l0, va);
    float4 n1 = interp8(l1, vb);

    // Pair 2: V64 + V128.
    Lv l2 = prep(V64, 64, px, py, pz);
    Lv l3 = prep(V128, 128, px, py, pz);
    do_loads8(l2, va);
    do_loads8(l3, vb);
    float4 n2 = interp8(l2, va);
    float4 n3 = interp8(l3, vb);

    float4 acc;
    acc.x = fmaf(0.125f, n3.x, fmaf(0.25f, n2.x, fmaf(0.5f, n1.x, n0.x)));
    acc.y = fmaf(0.125f, n3.y, fmaf(0.25f, n2.y, fmaf(0.5f, n1.y, n0.y)));
    acc.z = fmaf(0.125f, n3.z, fmaf(0.25f, n2.z, fmaf(0.5f, n1.z, n0.z)));
    acc.w = fmaf(0.125f, n3.w, fmaf(0.25f, n2.w, fmaf(0.5f, n1.w, n0.w)));

    reinterpret_cast<float4*>(out)[idx] = acc;
}

extern "C" void kernel_launch(void* const* d_in, const int* in_sizes, int n_in,
                              void* d_out, int out_size) {
    const float* x    = (const float*)d_in[0];
    const float* V16  = (const float*)d_in[1];
    const float* V32  = (const float*)d_in[2];
    const float* V64  = (const float*)d_in[3];
    const float* V128 = (const float*)d_in[4];
    float* out = (float*)d_out;

    int n = in_sizes[0] / 3;
    const int T = 256;
    int nquads = (n + 3) / 4;

    zero_hist_kernel<<<(NBUCK / 4 + T - 1) / T, T>>>();
    hist_kernel<<<(nquads + T - 1) / T, T>>>(x, n);
    scan1_kernel<<<SCAN_BLKS, 256>>>();
    scatter_kernel<<<(nquads + T - 1) / T, T>>>(x, n);

    int blocks = (n + T - 1) / T;
    composite_value_noise_kernel<<<blocks, T>>>(V16, V32, V64, V128, out, n);
}